// round 10
// baseline (speedup 1.0000x reference)
#include <cuda_runtime.h>

#define TK_D       16384
#define TK_THREADS 256
#define TK_CHUNK   (TK_THREADS * 4)          // 1024 elements per iteration
#define TK_NITER   (TK_D / TK_CHUNK)         // 16
#define TK_CAP     512
#define TK_ZGRID   592                       // zero-writer CTAs (148 x 4)
#define TK_SGRID   592                       // selector CTAs   (148 x 4)
#define TK_MAXROWS 8192

// Compact winner exchange: (ordered_key << 32) | (D-1-idx), exactly k per row.
__device__ unsigned long long g_win[(size_t)TK_MAXROWS * TK_CAP];
__device__ int g_cnt[TK_MAXROWS];

struct TKShared {
    unsigned long long cand[TK_CAP];
    int cnt;
    int red;
};

// Order-preserving float->uint key: larger float <=> larger key.
__device__ __forceinline__ unsigned f2k(float f) {
    unsigned b = __float_as_uint(f);
    return b ^ ((unsigned)((int)b >> 31) | 0x80000000u);
}
__device__ __forceinline__ float k2f(unsigned u) {
    unsigned b = u ^ ((u & 0x80000000u) ? 0x80000000u : 0xFFFFFFFFu);
    return __uint_as_float(b);
}

__device__ __forceinline__ void tk_push(TKShared* sm, unsigned u, int idx) {
    int p = atomicAdd(&sm->cnt, 1);
    if (p < TK_CAP)
        sm->cand[p] = ((unsigned long long)u << 32) | (unsigned)(TK_D - 1 - idx);
}

// Deferred candidate collection: revisit only flagged chunks (~0.5 per thread,
// L2-resident because the stream used default caching).
__device__ void tk_collect(const float* __restrict__ rp, float tlo, unsigned mask,
                           TKShared* sm, int tid) {
    while (mask) {
        int c = __ffs(mask) - 1;
        mask &= mask - 1;
        int base = c * TK_CHUNK + tid * 4;
        float4 v = *(const float4*)(rp + base);
        if (v.x > tlo) tk_push(sm, f2k(v.x), base + 0);
        if (v.y > tlo) tk_push(sm, f2k(v.y), base + 1);
        if (v.z > tlo) tk_push(sm, f2k(v.z), base + 2);
        if (v.w > tlo) tk_push(sm, f2k(v.w), base + 3);
    }
}

// Key-space scan: push keys in (klo, khi]. Fallback paths only.
__device__ void tk_scank(const float* __restrict__ rp,
                         unsigned klo, unsigned khi, TKShared* sm, int tid) {
    #pragma unroll 2
    for (int c = 0; c < TK_NITER; c++) {
        int base = c * TK_CHUNK + tid * 4;
        float4 v = *(const float4*)(rp + base);
        unsigned u0 = f2k(v.x), u1 = f2k(v.y), u2 = f2k(v.z), u3 = f2k(v.w);
        if (u0 > klo && u0 <= khi) tk_push(sm, u0, base + 0);
        if (u1 > klo && u1 <= khi) tk_push(sm, u1, base + 1);
        if (u2 > klo && u2 <= khi) tk_push(sm, u2, base + 2);
        if (u3 > klo && u3 <= khi) tk_push(sm, u3, base + 3);
    }
}

// mode 0: count keys > a ; mode 1: count (key == a && idx <= b). Block-wide.
__device__ int tk_count(const float* __restrict__ rp, unsigned a, int b, int mode,
                        TKShared* sm, int tid) {
    __syncthreads();
    if (tid == 0) sm->red = 0;
    __syncthreads();
    int c = 0;
    #pragma unroll 2
    for (int ch = 0; ch < TK_NITER; ch++) {
        int base = ch * TK_CHUNK + tid * 4;
        float4 v = *(const float4*)(rp + base);
        unsigned u0 = f2k(v.x), u1 = f2k(v.y), u2 = f2k(v.z), u3 = f2k(v.w);
        if (mode == 0) {
            c += (int)(u0 > a) + (int)(u1 > a) + (int)(u2 > a) + (int)(u3 > a);
        } else {
            c += (int)(u0 == a && base + 0 <= b) + (int)(u1 == a && base + 1 <= b)
               + (int)(u2 == a && base + 2 <= b) + (int)(u3 == a && base + 3 <= b);
        }
    }
    #pragma unroll
    for (int o = 16; o > 0; o >>= 1) c += __shfl_xor_sync(0xffffffffu, c, o);
    if ((tid & 31) == 0) atomicAdd(&sm->red, c);
    __syncthreads();
    return sm->red;
}

// Exact selection: candidate i wins iff fewer than k candidates have a larger
// packed key. Keys unique (index embedded) -> exactly min(c,k) winners, emitted
// by rank into the compact buffer.
__device__ void tk_rank_emit(TKShared* sm, int c, int k, int row, int tid) {
    unsigned long long* wrow = g_win + (size_t)row * TK_CAP;
    for (int i = tid; i < c; i += TK_THREADS) {
        unsigned long long K = sm->cand[i];
        int r = 0;
        for (int j = 0; j < c; j++)
            r += (sm->cand[j] > K) ? 1 : 0;
        if (r < k) wrow[r] = K;
    }
}

// Cold fallback for one row (never taken on N(0,1) data). Block-uniform.
__device__ void tk_cold_row(const float* __restrict__ rp, TKShared* sm,
                            int cnt, int k, float tlo, int row, int tid) {
    unsigned lo_key = f2k(tlo);
    unsigned hi_key = 0xFFFFFFFFu;      // count(key > hi_key) == 0 < k

    // Undershoot ladder in key space.
    {
        const unsigned krungs[6] = {f2k(1.2f), f2k(0.0f), f2k(-1.2f),
                                    f2k(-2.8f), f2k(-8.0f), 0u};
        int ki = 0;
        while (cnt < k && ki < 6) {
            unsigned k_new = krungs[ki];
            tk_scank(rp, k_new, lo_key, sm, tid);
            __syncthreads();
            cnt = sm->cnt;
            hi_key = lo_key;
            lo_key = k_new;
            ki++;
        }
    }

    if (cnt >= k && cnt <= TK_CAP) {
        tk_rank_emit(sm, cnt, k, row, tid);
        __syncthreads();
        return;
    }

    // Overflow: key-space bisection.
    unsigned lo = lo_key;
    while (hi_key - lo > 1u) {
        unsigned mid = lo + (hi_key - lo) / 2u;
        int cm = tk_count(rp, mid, 0, 0, sm, tid);
        if (cm < k) {
            hi_key = mid;
        } else if (cm <= TK_CAP) {
            __syncthreads();
            if (tid == 0) sm->cnt = 0;
            __syncthreads();
            tk_scank(rp, mid, 0xFFFFFFFFu, sm, tid);
            __syncthreads();
            tk_rank_emit(sm, sm->cnt, k, row, tid);
            __syncthreads();
            return;
        } else {
            lo = mid;
        }
    }

    // Massive-duplicate case: the k-th largest key is exactly hi_key.
    int cgt = tk_count(rp, hi_key, 0, 0, sm, tid);   // strictly greater, < k
    int needed = k - cgt;

    // Emit all strict winners at ranks 0..cgt-1.
    __syncthreads();
    if (tid == 0) sm->cnt = 0;
    __syncthreads();
    tk_scank(rp, hi_key, 0xFFFFFFFFu, sm, tid);
    __syncthreads();
    tk_rank_emit(sm, sm->cnt, k, row, tid);

    // Among keys == hi_key, take the `needed` smallest indices (idx unique ->
    // exactly `needed` elements with idx <= ihi): bisect the index cutoff.
    int ilo = -1, ihi = TK_D - 1;
    while (ihi - ilo > 1) {
        int im = (ilo + ihi) / 2;
        int ce = tk_count(rp, hi_key, im, 1, sm, tid);
        if (ce >= needed) ihi = im; else ilo = im;
    }
    __syncthreads();
    if (tid == 0) sm->red = cgt;        // slot counter for equal-key emits
    __syncthreads();
    unsigned long long* wrow = g_win + (size_t)row * TK_CAP;
    #pragma unroll 2
    for (int ch = 0; ch < TK_NITER; ch++) {
        int base = ch * TK_CHUNK + tid * 4;
        float4 v = *(const float4*)(rp + base);
        #pragma unroll
        for (int e = 0; e < 4; e++) {
            float f = (e == 0) ? v.x : (e == 1) ? v.y : (e == 2) ? v.z : v.w;
            int idx = base + e;
            if (f2k(f) == hi_key && idx <= ihi) {
                int s = atomicAdd(&sm->red, 1);
                if (s < k)
                    wrow[s] = ((unsigned long long)hi_key << 32)
                            | (unsigned)(TK_D - 1 - idx);
            }
        }
    }
    __syncthreads();
}

// FUSED KERNEL — CTA-role partition guarantees read/write concurrency:
//   blocks [0, TK_ZGRID)                : pure WRITE stream (zero output)
//   blocks [TK_ZGRID, TK_ZGRID+TK_SGRID): pure READ stream (persistent select)
// Each SM hosts ~4 CTAs of each role; every SMSP runs a pure loop and the
// read/write mixing happens only at the memory controllers.
__global__ __launch_bounds__(TK_THREADS, 8)
void tk_fused_kernel(const float* __restrict__ in,
                     const int* __restrict__ kptr,
                     float4* __restrict__ outq, long long nquads,
                     int nrows) {
    const int tid = threadIdx.x;

    if (blockIdx.x < TK_ZGRID) {
        // ---------------- ZERO ROLE: pure write stream ----------------
        long long i = (long long)blockIdx.x * TK_THREADS + tid;
        const long long stride = (long long)TK_ZGRID * TK_THREADS;
        const float4 z = make_float4(0.f, 0.f, 0.f, 0.f);
        #pragma unroll 4
        for (; i < nquads; i += stride)
            __stcs(outq + i, z);
        return;
    }

    // ---------------- SELECT ROLE: pure read stream ----------------
    __shared__ TKShared pool[2];
    const int sb = blockIdx.x - TK_ZGRID;     // 0 .. TK_SGRID-1

    int k = kptr ? *kptr : 64;
    if (k < 1) k = 1;
    if (k > TK_CAP) k = TK_CAP;

    if (tid == 0) { pool[0].cnt = 0; pool[1].cnt = 0; }
    __syncthreads();

    const float TLO = 2.4f;
    int p = 0;

    for (int row = sb; row < nrows; row += TK_SGRID) {
        const float* rp = in + (size_t)row * TK_D;
        TKShared* sm = &pool[p];

        // Stream the row: flag quads with x > 2.4. For iid N(0,1),
        // E[count] ~= 134/row, sd ~= 11.6: 64 <= cnt <= 512 at >20 sigma.
        unsigned mask = 0;
        #pragma unroll 4
        for (int c = 0; c < TK_NITER; c++) {
            int base = c * TK_CHUNK + tid * 4;
            float4 v = *(const float4*)(rp + base);
            float m = fmaxf(fmaxf(v.x, v.y), fmaxf(v.z, v.w));
            if (m > TLO) mask |= (1u << c);
        }
        if (mask) tk_collect(rp, TLO, mask, sm, tid);

        __syncthreads();                       // all pushes for this row done
        int cnt = sm->cnt;
        if (tid == 0) {
            pool[p ^ 1].cnt = 0;               // prep next row's pool
            g_cnt[row] = k;                    // every path emits exactly k
        }
        __syncthreads();                       // reset visible before any push

        if (cnt >= k && cnt <= TK_CAP) {
            // Fast path. No trailing barrier: threads with tid >= cnt proceed
            // straight into the next row's load stream; pool p is reused only
            // at row+2, after two barriers.
            tk_rank_emit(sm, cnt, k, row, tid);
        } else {
            tk_cold_row(rp, sm, cnt, k, TLO, row, tid);
        }
        p ^= 1;
    }
}

// Tiny scatter of the k winners per row (~16 MB of sectors, partly L2-hit).
__global__ __launch_bounds__(TK_THREADS)
void tk_scatter_kernel(float* __restrict__ out, int nrows) {
    for (int row = blockIdx.x; row < nrows; row += gridDim.x) {
        int n = g_cnt[row];
        if (n > TK_CAP) n = TK_CAP;
        float* op = out + (size_t)row * TK_D;
        for (int i = threadIdx.x; i < n; i += TK_THREADS) {
            unsigned long long w = g_win[(size_t)row * TK_CAP + i];
            int idx = TK_D - 1 - (int)(w & 0xFFFFFFFFu);
            op[idx] = k2f((unsigned)(w >> 32));
        }
    }
}

extern "C" void kernel_launch(void* const* d_in, const int* in_sizes, int n_in,
                              void* d_out, int out_size) {
    const float* in = (const float*)d_in[0];
    const int*   kp = (n_in > 1) ? (const int*)d_in[1] : nullptr;
    int N = in_sizes[0] / TK_D;          // 8192 rows
    if (N > TK_MAXROWS) N = TK_MAXROWS;

    long long nquads = (long long)out_size / 4;

    // Node 1: fused zero-writer + selector kernel (guaranteed co-residency).
    tk_fused_kernel<<<TK_ZGRID + TK_SGRID, TK_THREADS>>>(
        in, kp, (float4*)d_out, nquads, N);

    // Node 2: scatter winners into the zeroed output.
    tk_scatter_kernel<<<1184, TK_THREADS>>>((float*)d_out, N);
}

// round 11
// speedup vs baseline: 1.1714x; 1.1714x over previous
#include <cuda_runtime.h>

#define TK_D       16384
#define TK_THREADS 256
#define TK_CHUNK   (TK_THREADS * 4)          // 1024 elements per iteration
#define TK_NITER   (TK_D / TK_CHUNK)         // 16
#define TK_CAP     512
#define TK_GRID    1184                      // 148 SMs x 8 CTAs: one wave
#define TK_NPOOL   3

struct TKShared {
    unsigned long long cand[TK_CAP];   // (ordered_key << 32) | (D-1-idx)
    int cnt;
    int red;
};

// Order-preserving float->uint key: larger float <=> larger key.
__device__ __forceinline__ unsigned f2k(float f) {
    unsigned b = __float_as_uint(f);
    return b ^ ((unsigned)((int)b >> 31) | 0x80000000u);
}
__device__ __forceinline__ float k2f(unsigned u) {
    unsigned b = u ^ ((u & 0x80000000u) ? 0x80000000u : 0xFFFFFFFFu);
    return __uint_as_float(b);
}

__device__ __forceinline__ void tk_push(TKShared* sm, unsigned u, int idx) {
    int p = atomicAdd(&sm->cnt, 1);
    if (p < TK_CAP)
        sm->cand[p] = ((unsigned long long)u << 32) | (unsigned)(TK_D - 1 - idx);
}

// Deferred candidate collection: revisit only flagged chunks (~0.5 per thread,
// L2-resident because the stream used default caching).
__device__ void tk_collect(const float* __restrict__ rp, float tlo, unsigned mask,
                           TKShared* sm, int tid) {
    while (mask) {
        int c = __ffs(mask) - 1;
        mask &= mask - 1;
        int base = c * TK_CHUNK + tid * 4;
        float4 v = *(const float4*)(rp + base);
        if (v.x > tlo) tk_push(sm, f2k(v.x), base + 0);
        if (v.y > tlo) tk_push(sm, f2k(v.y), base + 1);
        if (v.z > tlo) tk_push(sm, f2k(v.z), base + 2);
        if (v.w > tlo) tk_push(sm, f2k(v.w), base + 3);
    }
}

// Key-space scan: push keys in (klo, khi]. Fallback paths only.
__device__ void tk_scank(const float* __restrict__ rp,
                         unsigned klo, unsigned khi, TKShared* sm, int tid) {
    #pragma unroll 2
    for (int c = 0; c < TK_NITER; c++) {
        int base = c * TK_CHUNK + tid * 4;
        float4 v = *(const float4*)(rp + base);
        unsigned u0 = f2k(v.x), u1 = f2k(v.y), u2 = f2k(v.z), u3 = f2k(v.w);
        if (u0 > klo && u0 <= khi) tk_push(sm, u0, base + 0);
        if (u1 > klo && u1 <= khi) tk_push(sm, u1, base + 1);
        if (u2 > klo && u2 <= khi) tk_push(sm, u2, base + 2);
        if (u3 > klo && u3 <= khi) tk_push(sm, u3, base + 3);
    }
}

// mode 0: count keys > a ; mode 1: count (key == a && idx <= b). Block-wide.
__device__ int tk_count(const float* __restrict__ rp, unsigned a, int b, int mode,
                        TKShared* sm, int tid) {
    __syncthreads();
    if (tid == 0) sm->red = 0;
    __syncthreads();
    int c = 0;
    #pragma unroll 2
    for (int ch = 0; ch < TK_NITER; ch++) {
        int base = ch * TK_CHUNK + tid * 4;
        float4 v = *(const float4*)(rp + base);
        unsigned u0 = f2k(v.x), u1 = f2k(v.y), u2 = f2k(v.z), u3 = f2k(v.w);
        if (mode == 0) {
            c += (int)(u0 > a) + (int)(u1 > a) + (int)(u2 > a) + (int)(u3 > a);
        } else {
            c += (int)(u0 == a && base + 0 <= b) + (int)(u1 == a && base + 1 <= b)
               + (int)(u2 == a && base + 2 <= b) + (int)(u3 == a && base + 3 <= b);
        }
    }
    #pragma unroll
    for (int o = 16; o > 0; o >>= 1) c += __shfl_xor_sync(0xffffffffu, c, o);
    if ((tid & 31) == 0) atomicAdd(&sm->red, c);
    __syncthreads();
    return sm->red;
}

// Exact selection: candidate i wins iff fewer than k candidates have a larger
// packed key. Keys unique (index embedded) -> exactly min(c,k) winners.
// Inner reads are warp-uniform -> smem broadcast (conflict-free). Only threads
// with tid < c do work; the rest fall through to the next row's stream.
__device__ void tk_rank_scatter(TKShared* sm, int c, int k, float* __restrict__ op, int tid) {
    for (int i = tid; i < c; i += TK_THREADS) {
        unsigned long long K = sm->cand[i];
        int r = 0;
        for (int j = 0; j < c; j++)
            r += (sm->cand[j] > K) ? 1 : 0;
        if (r < k) {
            unsigned u = (unsigned)(K >> 32);
            int idx = TK_D - 1 - (int)(K & 0xFFFFFFFFu);
            op[idx] = k2f(u);
        }
    }
}

// Cold fallback for one row (never taken on N(0,1) data). Block-uniform
// control flow; internal __syncthreads are safe. Ends with a barrier so the
// 3-pool rotation invariants hold trivially on this path.
__device__ void tk_cold_row(const float* __restrict__ rp, float* __restrict__ op,
                            TKShared* sm, int cnt, int k, float tlo, int tid) {
    unsigned lo_key = f2k(tlo);
    unsigned hi_key = 0xFFFFFFFFu;      // count(key > hi_key) == 0 < k

    // Undershoot ladder in key space.
    {
        const unsigned krungs[6] = {f2k(1.2f), f2k(0.0f), f2k(-1.2f),
                                    f2k(-2.8f), f2k(-8.0f), 0u};
        int ki = 0;
        while (cnt < k && ki < 6) {
            unsigned k_new = krungs[ki];
            tk_scank(rp, k_new, lo_key, sm, tid);
            __syncthreads();
            cnt = sm->cnt;
            hi_key = lo_key;
            lo_key = k_new;
            ki++;
        }
    }

    if (cnt >= k && cnt <= TK_CAP) {
        tk_rank_scatter(sm, cnt, k, op, tid);
        __syncthreads();
        return;
    }

    // Overflow: key-space bisection.
    // Invariants: count(key > lo_key) >= cnt > CAP >= k ; count(key > hi_key) < k.
    unsigned lo = lo_key;
    while (hi_key - lo > 1u) {
        unsigned mid = lo + (hi_key - lo) / 2u;
        int cm = tk_count(rp, mid, 0, 0, sm, tid);
        if (cm < k) {
            hi_key = mid;
        } else if (cm <= TK_CAP) {
            __syncthreads();
            if (tid == 0) sm->cnt = 0;
            __syncthreads();
            tk_scank(rp, mid, 0xFFFFFFFFu, sm, tid);
            __syncthreads();
            tk_rank_scatter(sm, sm->cnt, k, op, tid);
            __syncthreads();
            return;
        } else {
            lo = mid;
        }
    }

    // Massive-duplicate case: the k-th largest key is exactly hi_key.
    int cgt = tk_count(rp, hi_key, 0, 0, sm, tid);   // strictly greater, < k
    int needed = k - cgt;

    // Scatter all strict winners (cgt < k <= CAP: they all fit & all win).
    __syncthreads();
    if (tid == 0) sm->cnt = 0;
    __syncthreads();
    tk_scank(rp, hi_key, 0xFFFFFFFFu, sm, tid);
    __syncthreads();
    tk_rank_scatter(sm, sm->cnt, k, op, tid);

    // Among keys == hi_key, take the `needed` smallest indices: bisect cutoff.
    int ilo = -1, ihi = TK_D - 1;
    while (ihi - ilo > 1) {
        int im = (ilo + ihi) / 2;
        int ce = tk_count(rp, hi_key, im, 1, sm, tid);
        if (ce >= needed) ihi = im; else ilo = im;
    }
    __syncthreads();
    #pragma unroll 2
    for (int ch = 0; ch < TK_NITER; ch++) {
        int base = ch * TK_CHUNK + tid * 4;
        float4 v = *(const float4*)(rp + base);
        if (f2k(v.x) == hi_key && base + 0 <= ihi) op[base + 0] = v.x;
        if (f2k(v.y) == hi_key && base + 1 <= ihi) op[base + 1] = v.y;
        if (f2k(v.z) == hi_key && base + 2 <= ihi) op[base + 2] = v.z;
        if (f2k(v.w) == hi_key && base + 3 <= ihi) op[base + 3] = v.w;
    }
    __syncthreads();
}

// Output rows are pre-zeroed by the memset graph node; this kernel only reads
// the input and scatters the k winners. PERSISTENT CTAs with a 3-pool rotation
// and ONE barrier per row:
//   - row r uses pool r%3; tid0 resets pool (r+1)%3 BEFORE the barrier. That
//     pool's last user was row r-2, whose selection completed before row r-1's
//     barrier (every thread finishes selection of row q before streaming row
//     q+1 and arriving at row q+1's barrier), so the reset is race-free. The
//     barrier then publishes the reset before row r+1's pushes.
//   - Fast-path selection has no trailing barrier: threads with tid >= cnt
//     start row r+1's loads immediately, hiding the select tail. Pool r%3 is
//     reused only at row r+3.
__global__ __launch_bounds__(TK_THREADS, 8)
void TopKActivation_68324339745162_kernel(const float* __restrict__ in,
                                          const int* __restrict__ kptr,
                                          float* __restrict__ out,
                                          int nrows) {
    __shared__ TKShared pool[TK_NPOOL];
    const int tid = threadIdx.x;

    int k = kptr ? *kptr : 64;
    if (k < 1) k = 1;
    if (k > TK_CAP) k = TK_CAP;

    if (tid == 0) {
        pool[0].cnt = 0; pool[1].cnt = 0; pool[2].cnt = 0;
    }
    __syncthreads();

    const float TLO = 2.4f;
    int p = 0;

    for (int row = blockIdx.x; row < nrows; row += gridDim.x) {
        const float* rp = in + (size_t)row * TK_D;
        float*       op = out + (size_t)row * TK_D;
        TKShared* sm = &pool[p];

        // ---- Stream the row: flag quads with x > 2.4. For iid N(0,1),
        // E[count] ~= 134/row, sd ~= 11.6: 64 <= cnt <= 512 at >20 sigma.
        unsigned mask = 0;
        #pragma unroll 4
        for (int c = 0; c < TK_NITER; c++) {
            int base = c * TK_CHUNK + tid * 4;
            float4 v = *(const float4*)(rp + base);
            float m = fmaxf(fmaxf(v.x, v.y), fmaxf(v.z, v.w));
            if (m > TLO) mask |= (1u << c);
        }
        if (mask) tk_collect(rp, TLO, mask, sm, tid);

        // Reset NEXT row's pool before the barrier (see rotation proof above).
        if (tid == 0) {
            int np = p + 1; if (np == TK_NPOOL) np = 0;
            pool[np].cnt = 0;
        }
        __syncthreads();                 // pushes done + reset published
        int cnt = sm->cnt;

        if (cnt >= k && cnt <= TK_CAP) {
            // Fast path: exact rank selection, fused scatter. No trailing
            // barrier — idle threads flow straight into the next row's loads.
            tk_rank_scatter(sm, cnt, k, op, tid);
        } else {
            tk_cold_row(rp, op, sm, cnt, k, TLO, tid);
        }
        p++; if (p == TK_NPOOL) p = 0;
    }
}

extern "C" void kernel_launch(void* const* d_in, const int* in_sizes, int n_in,
                              void* d_out, int out_size) {
    const float* in = (const float*)d_in[0];
    const int*   kp = (n_in > 1) ? (const int*)d_in[1] : nullptr;
    int N = in_sizes[0] / TK_D;          // 8192 rows

    // Node 1: pure-write stream — zero the whole output (~6.5 TB/s).
    cudaMemsetAsync(d_out, 0, (size_t)out_size * sizeof(float), 0);

    // Node 2: pure-read stream — persistent CTAs, select + fused scatter.
    int grid = (N < TK_GRID) ? N : TK_GRID;
    TopKActivation_68324339745162_kernel<<<grid, TK_THREADS>>>(in, kp, (float*)d_out, N);
}